// round 5
// baseline (speedup 1.0000x reference)
#include <cuda_runtime.h>
#include <math.h>

#define NNODES 50000
#define NEDGES 800000
#define NG     512
#define EPSBN  1e-5f
#define SCAN_B 512
#define NSCB   ((NNODES + SCAN_B - 1) / SCAN_B)   // 98

// ---------------- scratch (device globals; 16B-aligned by type) --------------
__device__ float4       g_T4 [NNODES * 64];   // transform output  h @ W (256 f)
__device__ float4       g_H14[NNODES * 64];   // layer activations (ping)
__device__ float4       g_H24[NNODES * 64];   // layer activations (pong)
__device__ int          g_cnt[NNODES];
__device__ int          g_off[NNODES + 1];
__device__ int          g_curs[NNODES];
__device__ float        g_dis[NNODES];
__device__ int          g_srcS[NEDGES];
__device__ float        g_normS[NEDGES];
__device__ int          g_bsum[NSCB];
__device__ int          g_boff[NSCB];
__device__ float        g_psum[NG * 256];
__device__ unsigned int g_pmax[NG * 256];
__device__ float        g_pcnt[NG];
__device__ float        g_z  [NG * 512];
__device__ float        g_m1 [NG * 256];
__device__ float        g_m2 [NG * 128];

// ---------------- graph preprocessing ----------------------------------------
__global__ void zero_kernel() {
    int i = blockIdx.x * blockDim.x + threadIdx.x;   // covers 131072
    if (i < NNODES)    g_cnt[i] = 0;
    if (i < NG * 256) { g_psum[i] = 0.f; g_pmax[i] = 0u; }
    if (i < NG)        g_pcnt[i] = 0.f;
}

__global__ void count_kernel(const int* __restrict__ dst) {
    int e = blockIdx.x * blockDim.x + threadIdx.x;
    if (e < NEDGES) atomicAdd(&g_cnt[dst[e]], 1);
}

// --- hierarchical exclusive scan of g_cnt -> g_off ---------------------------
__global__ void scanA_kernel() {     // per-chunk scan + chunk totals
    __shared__ int sh[SCAN_B];
    int t = threadIdx.x;
    int i = blockIdx.x * SCAN_B + t;
    int v = (i < NNODES) ? g_cnt[i] : 0;
    sh[t] = v;
    __syncthreads();
#pragma unroll
    for (int d = 1; d < SCAN_B; d <<= 1) {
        int u = (t >= d) ? sh[t - d] : 0;
        __syncthreads();
        sh[t] += u;
        __syncthreads();
    }
    if (i < NNODES) g_off[i] = sh[t] - v;          // chunk-local exclusive
    if (t == SCAN_B - 1) g_bsum[blockIdx.x] = sh[t];
}

__global__ void scanB_kernel() {     // scan the 98 chunk totals (1 block)
    __shared__ int sh[128];
    int t = threadIdx.x;
    int v = (t < NSCB) ? g_bsum[t] : 0;
    sh[t] = v;
    __syncthreads();
#pragma unroll
    for (int d = 1; d < 128; d <<= 1) {
        int u = (t >= d) ? sh[t - d] : 0;
        __syncthreads();
        sh[t] += u;
        __syncthreads();
    }
    if (t < NSCB) g_boff[t] = sh[t] - v;           // exclusive
}

__global__ void scanC_kernel() {     // add chunk offsets + cursors + dis
    int i = blockIdx.x * blockDim.x + threadIdx.x;
    if (i < NNODES) {
        int o = g_off[i] + g_boff[i / SCAN_B];
        g_off[i]  = o;
        g_curs[i] = o;
        g_dis[i]  = rsqrtf((float)g_cnt[i] + 1.0f);   // +1 self loop
    }
    if (i == 0) g_off[NNODES] = NEDGES;
}

__global__ void fill_kernel(const int* __restrict__ src,
                            const int* __restrict__ dst) {
    int e = blockIdx.x * blockDim.x + threadIdx.x;
    if (e < NEDGES) {
        int s = src[e], d = dst[e];
        int p = atomicAdd(&g_curs[d], 1);
        g_srcS[p]  = s;
        g_normS[p] = g_dis[s] * g_dis[d];
    }
}

// ---------------- GEMM: C[M,Nn] = A[M,K] @ B[K,Nn] (+bias, +act) -------------
// 128x128 tile, BK=8, 256 threads, 8x8 per thread. Requires Nn % 128 == 0,
// K % 8 == 0. M edge guarded.
// ACT: 0=none, 1=exact GELU
// ASEL: 0=ext, 1=g_H14, 2=g_H24, 3=g_z, 4=g_m1
// CSEL: 0=ext, 1=g_T4, 2=g_m1, 3=g_m2
template <int ACT, int ASEL, int CSEL>
__global__ __launch_bounds__(256)
void gemm128_kernel(const float* __restrict__ Aext, const float* __restrict__ B,
                    const float* __restrict__ bias, float* __restrict__ Cext,
                    int M, int Nn, int K) {
    const float* A = (ASEL == 0) ? Aext :
                     (ASEL == 1) ? (const float*)g_H14 :
                     (ASEL == 2) ? (const float*)g_H24 :
                     (ASEL == 3) ? (const float*)g_z  : (const float*)g_m1;
    float* C = (CSEL == 0) ? Cext :
               (CSEL == 1) ? (float*)g_T4 :
               (CSEL == 2) ? (float*)g_m1 : (float*)g_m2;

    __shared__ float As[8][128];
    __shared__ float Bs[8][128];
    int tid = threadIdx.x;
    int m0 = blockIdx.x * 128;
    int n0 = blockIdx.y * 128;
    int tx = tid & 15, ty = tid >> 4;           // 16 x 16 thread grid

    // A load: arow = tid % 128 (warp covers 32 consecutive rows -> conflict-free STS)
    int arow = tid & 127, acol = (tid >> 7) * 4;
    // B load: warp loads one k-row contiguously (coalesced 512B)
    int brow = tid >> 5, bcol = (tid & 31) * 4;

    float acc[8][8] = {};
    for (int k0 = 0; k0 < K; k0 += 8) {
        float4 av = make_float4(0.f, 0.f, 0.f, 0.f);
        if (m0 + arow < M)
            av = *(const float4*)&A[(size_t)(m0 + arow) * K + k0 + acol];
        As[acol + 0][arow] = av.x;
        As[acol + 1][arow] = av.y;
        As[acol + 2][arow] = av.z;
        As[acol + 3][arow] = av.w;
        *(float4*)&Bs[brow][bcol] =
            *(const float4*)&B[(size_t)(k0 + brow) * Nn + n0 + bcol];
        __syncthreads();
#pragma unroll
        for (int k = 0; k < 8; k++) {
            float a[8], b[8];
            *(float4*)&a[0] = *(const float4*)&As[k][ty * 8];
            *(float4*)&a[4] = *(const float4*)&As[k][ty * 8 + 4];
            *(float4*)&b[0] = *(const float4*)&Bs[k][tx * 8];
            *(float4*)&b[4] = *(const float4*)&Bs[k][tx * 8 + 4];
#pragma unroll
            for (int i = 0; i < 8; i++)
#pragma unroll
                for (int j = 0; j < 8; j++) acc[i][j] += a[i] * b[j];
        }
        __syncthreads();
    }

    float bi[8];
#pragma unroll
    for (int j = 0; j < 8; j++) bi[j] = bias ? bias[n0 + tx * 8 + j] : 0.f;

#pragma unroll
    for (int i = 0; i < 8; i++) {
        int m = m0 + ty * 8 + i;
        if (m >= M) continue;
        float v[8];
#pragma unroll
        for (int j = 0; j < 8; j++) {
            float t = acc[i][j] + bi[j];
            if (ACT == 1) t = 0.5f * t * (1.0f + erff(t * 0.70710678118654752f));
            v[j] = t;
        }
        float* crow = &C[(size_t)m * Nn + n0 + tx * 8];
        *(float4*)&crow[0] = make_float4(v[0], v[1], v[2], v[3]);
        *(float4*)&crow[4] = make_float4(v[4], v[5], v[6], v[7]);
    }
}

// final MLP layer: out[G, 6] = g_m2[G, 128] @ Wm3[128, 6] + bm3
__global__ void mlp3_kernel(const float* __restrict__ Wm3,
                            const float* __restrict__ bm3,
                            float* __restrict__ out) {
    int idx = blockIdx.x * blockDim.x + threadIdx.x;
    if (idx >= NG * 6) return;
    int m = idx / 6, n = idx % 6;
    const float* row = &g_m2[m * 128];
    float s = 0.f;
#pragma unroll 8
    for (int k = 0; k < 128; k++) s += row[k] * Wm3[k * 6 + n];
    out[idx] = s + bm3[n];
}

// ---------------- GCN aggregation + bias + BN + ReLU --------------------------
// one group of D4 threads per dst node; d = 4*D4 features; no float atomics
// OSEL: 1 -> g_H14, 2 -> g_H24
template <int D4, int OSEL>
__global__ void agg_kernel(const float* __restrict__ b,  const float* __restrict__ ga,
                           const float* __restrict__ be, const float* __restrict__ mm,
                           const float* __restrict__ vv) {
    float4* out = (OSEL == 1) ? g_H14 : g_H24;
    constexpr int NODES = 256 / D4;
    int node = blockIdx.x * NODES + (threadIdx.x / D4);
    int c    = threadIdx.x & (D4 - 1);
    if (node >= NNODES) return;

    float dn = g_dis[node];
    float w0 = dn * dn;                          // self-loop norm
    float4 t = g_T4[(size_t)node * D4 + c];
    float4 acc = make_float4(t.x * w0, t.y * w0, t.z * w0, t.w * w0);

    int e0 = g_off[node], e1 = g_off[node + 1];
    for (int e = e0; e < e1; e++) {
        int   s = g_srcS[e];
        float w = g_normS[e];
        float4 ts = g_T4[(size_t)s * D4 + c];
        acc.x += ts.x * w; acc.y += ts.y * w;
        acc.z += ts.z * w; acc.w += ts.w * w;
    }

    float bb[4] = {b[c*4],  b[c*4+1],  b[c*4+2],  b[c*4+3]};
    float gg[4] = {ga[c*4], ga[c*4+1], ga[c*4+2], ga[c*4+3]};
    float eb[4] = {be[c*4], be[c*4+1], be[c*4+2], be[c*4+3]};
    float mu[4] = {mm[c*4], mm[c*4+1], mm[c*4+2], mm[c*4+3]};
    float va[4] = {vv[c*4], vv[c*4+1], vv[c*4+2], vv[c*4+3]};
    float4 o;
    o.x = fmaxf((acc.x + bb[0] - mu[0]) * (gg[0] * rsqrtf(va[0] + EPSBN)) + eb[0], 0.f);
    o.y = fmaxf((acc.y + bb[1] - mu[1]) * (gg[1] * rsqrtf(va[1] + EPSBN)) + eb[1], 0.f);
    o.z = fmaxf((acc.z + bb[2] - mu[2]) * (gg[2] * rsqrtf(va[2] + EPSBN)) + eb[2], 0.f);
    o.w = fmaxf((acc.w + bb[3] - mu[3]) * (gg[3] * rsqrtf(va[3] + EPSBN)) + eb[3], 0.f);
    out[(size_t)node * D4 + c] = o;
}

// ---------------- pooling (batch is sorted -> run-length flush) ---------------
__global__ void pool_feat_kernel(const int* __restrict__ batch) {
    int c  = threadIdx.x;                  // 0..63 float4 columns (d = 256)
    int i0 = blockIdx.x * 64;
    if (i0 >= NNODES) return;
    int i1 = min(i0 + 64, NNODES);
    int cur = batch[i0];
    float4 s  = make_float4(0, 0, 0, 0);
    float4 mx = make_float4(0, 0, 0, 0);
    for (int i = i0; i < i1; i++) {
        int g = batch[i];
        if (g != cur) {
            int base = cur * 256 + c * 4;
            atomicAdd(&g_psum[base + 0], s.x); atomicAdd(&g_psum[base + 1], s.y);
            atomicAdd(&g_psum[base + 2], s.z); atomicAdd(&g_psum[base + 3], s.w);
            atomicMax(&g_pmax[base + 0], __float_as_uint(mx.x));
            atomicMax(&g_pmax[base + 1], __float_as_uint(mx.y));
            atomicMax(&g_pmax[base + 2], __float_as_uint(mx.z));
            atomicMax(&g_pmax[base + 3], __float_as_uint(mx.w));
            cur = g; s = make_float4(0, 0, 0, 0); mx = make_float4(0, 0, 0, 0);
        }
        float4 hv = g_H14[(size_t)i * 64 + c];
        s.x += hv.x; s.y += hv.y; s.z += hv.z; s.w += hv.w;
        mx.x = fmaxf(mx.x, hv.x); mx.y = fmaxf(mx.y, hv.y);
        mx.z = fmaxf(mx.z, hv.z); mx.w = fmaxf(mx.w, hv.w);
    }
    int base = cur * 256 + c * 4;
    atomicAdd(&g_psum[base + 0], s.x); atomicAdd(&g_psum[base + 1], s.y);
    atomicAdd(&g_psum[base + 2], s.z); atomicAdd(&g_psum[base + 3], s.w);
    atomicMax(&g_pmax[base + 0], __float_as_uint(mx.x));
    atomicMax(&g_pmax[base + 1], __float_as_uint(mx.y));
    atomicMax(&g_pmax[base + 2], __float_as_uint(mx.z));
    atomicMax(&g_pmax[base + 3], __float_as_uint(mx.w));
}

__global__ void pool_cnt_kernel(const int* __restrict__ batch) {
    int t  = blockIdx.x * blockDim.x + threadIdx.x;
    int i0 = t * 64;
    if (i0 >= NNODES) return;
    int i1 = min(i0 + 64, NNODES);
    int cur = batch[i0];
    int run = 0;
    for (int i = i0; i < i1; i++) {
        int g = batch[i];
        if (g != cur) { atomicAdd(&g_pcnt[cur], (float)run); cur = g; run = 0; }
        run++;
    }
    atomicAdd(&g_pcnt[cur], (float)run);
}

__global__ void finalize_z_kernel() {
    int idx = blockIdx.x * blockDim.x + threadIdx.x;
    if (idx >= NG * 512) return;
    int g = idx >> 9, c = idx & 511;
    if (c < 256) g_z[idx] = g_psum[g * 256 + c] / fmaxf(g_pcnt[g], 1.0f);
    else         g_z[idx] = __uint_as_float(g_pmax[g * 256 + (c - 256)]);
}

// ---------------- launch ------------------------------------------------------
extern "C" void kernel_launch(void* const* d_in, const int* in_sizes, int n_in,
                              void* d_out, int out_size) {
    const float* x     = (const float*)d_in[0];
    const int*   ei    = (const int*)d_in[1];   // [2, E] as int32
    const int*   batch = (const int*)d_in[2];
    const float *W1 = (const float*)d_in[3],  *b1 = (const float*)d_in[4],
                *ga1 = (const float*)d_in[5], *be1 = (const float*)d_in[6],
                *m1 = (const float*)d_in[7],  *v1 = (const float*)d_in[8];
    const float *W2 = (const float*)d_in[9],  *b2 = (const float*)d_in[10],
                *ga2 = (const float*)d_in[11],*be2 = (const float*)d_in[12],
                *m2 = (const float*)d_in[13], *v2 = (const float*)d_in[14];
    const float *W3 = (const float*)d_in[15], *b3 = (const float*)d_in[16],
                *ga3 = (const float*)d_in[17],*be3 = (const float*)d_in[18],
                *m3 = (const float*)d_in[19], *v3 = (const float*)d_in[20];
    const float *Wm1 = (const float*)d_in[21], *bm1 = (const float*)d_in[22];
    const float *Wm2 = (const float*)d_in[23], *bm2 = (const float*)d_in[24];
    const float *Wm3 = (const float*)d_in[25], *bm3 = (const float*)d_in[26];
    float* out = (float*)d_out;

    const int* src = ei;
    const int* dst = ei + NEDGES;

    // preprocessing
    zero_kernel<<<512, 256>>>();
    count_kernel<<<(NEDGES + 255) / 256, 256>>>(dst);
    scanA_kernel<<<NSCB, SCAN_B>>>();
    scanB_kernel<<<1, 128>>>();
    scanC_kernel<<<(NNODES + 255) / 256, 256>>>();
    fill_kernel<<<(NEDGES + 255) / 256, 256>>>(src, dst);

    const int MB128 = (NNODES + 127) / 128;   // 391 row-tiles

    // layer 1: 64 -> 128   (A = x ext, C = g_T4)
    gemm128_kernel<0, 0, 1><<<dim3(MB128, 1), 256>>>(x, W1, nullptr, nullptr, NNODES, 128, 64);
    agg_kernel<32, 1><<<(NNODES + 7) / 8, 256>>>(b1, ga1, be1, m1, v1);
    // layer 2: 128 -> 256  (A = g_H14, C = g_T4)
    gemm128_kernel<0, 1, 1><<<dim3(MB128, 2), 256>>>(nullptr, W2, nullptr, nullptr, NNODES, 256, 128);
    agg_kernel<64, 2><<<(NNODES + 3) / 4, 256>>>(b2, ga2, be2, m2, v2);
    // layer 3: 256 -> 256  (A = g_H24, C = g_T4)
    gemm128_kernel<0, 2, 1><<<dim3(MB128, 2), 256>>>(nullptr, W3, nullptr, nullptr, NNODES, 256, 256);
    agg_kernel<64, 1><<<(NNODES + 3) / 4, 256>>>(b3, ga3, be3, m3, v3);

    // pooling (reads g_H14)
    pool_feat_kernel<<<(NNODES + 63) / 64, 64>>>(batch);
    pool_cnt_kernel<<<((NNODES + 63) / 64 + 255) / 256, 256>>>(batch);
    finalize_z_kernel<<<(NG * 512 + 255) / 256, 256>>>();

    // MLP head
    gemm128_kernel<1, 3, 2><<<dim3(4, 2), 256>>>(nullptr, Wm1, bm1, nullptr, NG, 256, 512);
    gemm128_kernel<1, 4, 3><<<dim3(4, 1), 256>>>(nullptr, Wm2, bm2, nullptr, NG, 128, 256);
    mlp3_kernel<<<(NG * 6 + 255) / 256, 256>>>(Wm3, bm3, out);
}

// round 7
// speedup vs baseline: 1.4712x; 1.4712x over previous
#include <cuda_runtime.h>
#include <math.h>

#define NNODES 50000
#define NEDGES 800000
#define NG     512
#define EPSBN  1e-5f
#define SCAN_B 512
#define NSCB   ((NNODES + SCAN_B - 1) / SCAN_B)   // 98

// ---------------- scratch (device globals; 16B-aligned by type) --------------
__device__ float4       g_T4 [NNODES * 64];   // transform output  h @ W (256 f)
__device__ float4       g_H14[NNODES * 64];   // layer activations (ping)
__device__ float4       g_H24[NNODES * 64];   // layer activations (pong)
__device__ int          g_cnt[NNODES];
__device__ int          g_off[NNODES + 1];
__device__ int          g_curs[NNODES];
__device__ float        g_dis[NNODES];
__device__ int          g_srcS[NEDGES];
__device__ float        g_normS[NEDGES];
__device__ int          g_bsum[NSCB];
__device__ int          g_boff[NSCB];
__device__ float        g_psum[NG * 256];
__device__ unsigned int g_pmax[NG * 256];
__device__ float        g_pcnt[NG];
__device__ float        g_z  [NG * 512];
__device__ float        g_m1 [NG * 256];
__device__ float        g_m2 [NG * 128];

// ---------------- packed f32x2 helpers (Blackwell FFMA2 path) ----------------
__device__ __forceinline__ unsigned long long pk2(float lo, float hi) {
    unsigned long long r;
    asm("mov.b64 %0, {%1, %2};" : "=l"(r) : "f"(lo), "f"(hi));
    return r;
}
__device__ __forceinline__ void fma2(unsigned long long& d,
                                     unsigned long long a, unsigned long long b) {
    asm("fma.rn.f32x2 %0, %1, %2, %3;" : "=l"(d) : "l"(a), "l"(b), "l"(d));
}
__device__ __forceinline__ float2 upk2(unsigned long long v) {
    float2 f;
    asm("mov.b64 {%0, %1}, %2;" : "=f"(f.x), "=f"(f.y) : "l"(v));
    return f;
}

// ---------------- graph preprocessing ----------------------------------------
__global__ void zero_kernel() {
    int i = blockIdx.x * blockDim.x + threadIdx.x;   // covers 131072
    if (i < NNODES)    g_cnt[i] = 0;
    if (i < NG * 256) { g_psum[i] = 0.f; g_pmax[i] = 0u; }
    if (i < NG)        g_pcnt[i] = 0.f;
}

__global__ void count_kernel(const int* __restrict__ dst) {
    int e = blockIdx.x * blockDim.x + threadIdx.x;
    if (e < NEDGES) atomicAdd(&g_cnt[dst[e]], 1);
}

// --- hierarchical exclusive scan of g_cnt -> g_off ---------------------------
__global__ void scanA_kernel() {     // per-chunk scan + chunk totals
    __shared__ int sh[SCAN_B];
    int t = threadIdx.x;
    int i = blockIdx.x * SCAN_B + t;
    int v = (i < NNODES) ? g_cnt[i] : 0;
    sh[t] = v;
    __syncthreads();
#pragma unroll
    for (int d = 1; d < SCAN_B; d <<= 1) {
        int u = (t >= d) ? sh[t - d] : 0;
        __syncthreads();
        sh[t] += u;
        __syncthreads();
    }
    if (i < NNODES) g_off[i] = sh[t] - v;          // chunk-local exclusive
    if (t == SCAN_B - 1) g_bsum[blockIdx.x] = sh[t];
}

__global__ void scanB_kernel() {     // scan the 98 chunk totals (1 block)
    __shared__ int sh[128];
    int t = threadIdx.x;
    int v = (t < NSCB) ? g_bsum[t] : 0;
    sh[t] = v;
    __syncthreads();
#pragma unroll
    for (int d = 1; d < 128; d <<= 1) {
        int u = (t >= d) ? sh[t - d] : 0;
        __syncthreads();
        sh[t] += u;
        __syncthreads();
    }
    if (t < NSCB) g_boff[t] = sh[t] - v;           // exclusive
}

__global__ void scanC_kernel() {     // add chunk offsets + cursors + dis
    int i = blockIdx.x * blockDim.x + threadIdx.x;
    if (i < NNODES) {
        int o = g_off[i] + g_boff[i / SCAN_B];
        g_off[i]  = o;
        g_curs[i] = o;
        g_dis[i]  = rsqrtf((float)g_cnt[i] + 1.0f);   // +1 self loop
    }
    if (i == 0) g_off[NNODES] = NEDGES;
}

__global__ void fill_kernel(const int* __restrict__ src,
                            const int* __restrict__ dst) {
    int e = blockIdx.x * blockDim.x + threadIdx.x;
    if (e < NEDGES) {
        int s = src[e], d = dst[e];
        int p = atomicAdd(&g_curs[d], 1);
        g_srcS[p]  = s;
        g_normS[p] = g_dis[s] * g_dis[d];
    }
}

// ---------------- GEMM: C[M,Nn] = A[M,K] @ B[K,Nn] (+bias, +act) -------------
// 64x64 tile, BK=16, 256 threads, 4x4 per thread, packed f32x2 FMA inner loop.
// ACT: 0=none, 1=exact GELU
// ASEL: 0=ext, 1=g_H14, 2=g_H24, 3=g_z, 4=g_m1
// CSEL: 0=ext, 1=g_T4, 2=g_m1, 3=g_m2
template <int ACT, int ASEL, int CSEL>
__global__ void gemm_kernel(const float* __restrict__ Aext, const float* __restrict__ B,
                            const float* __restrict__ bias, float* __restrict__ Cext,
                            int M, int Nn, int K) {
    const float* A = (ASEL == 0) ? Aext :
                     (ASEL == 1) ? (const float*)g_H14 :
                     (ASEL == 2) ? (const float*)g_H24 :
                     (ASEL == 3) ? (const float*)g_z  : (const float*)g_m1;
    float* C = (CSEL == 0) ? Cext :
               (CSEL == 1) ? (float*)g_T4 :
               (CSEL == 2) ? (float*)g_m1 : (float*)g_m2;

    __shared__ float As[16][64];
    __shared__ float Bs[16][64];
    int tid = threadIdx.x;
    int tx = tid & 15, ty = tid >> 4;
    int m0 = blockIdx.x * 64;
    int n0 = blockIdx.y * 64;

    unsigned long long acc2[4][2];
#pragma unroll
    for (int i = 0; i < 4; i++) { acc2[i][0] = 0ull; acc2[i][1] = 0ull; }

    for (int k0 = 0; k0 < K; k0 += 16) {
#pragma unroll
        for (int r = 0; r < 4; r++) {
            int idx = tid + r * 256;
            int m = idx >> 4, k = idx & 15;
            int gm = m0 + m;
            As[k][m] = (gm < M) ? A[(size_t)gm * K + k0 + k] : 0.f;
        }
#pragma unroll
        for (int r = 0; r < 4; r++) {
            int idx = tid + r * 256;
            int k = idx >> 6, n = idx & 63;
            int gn = n0 + n;
            Bs[k][n] = (gn < Nn) ? B[(size_t)(k0 + k) * Nn + gn] : 0.f;
        }
        __syncthreads();
#pragma unroll
        for (int k = 0; k < 16; k++) {
            unsigned long long b0 = *(const unsigned long long*)&Bs[k][tx * 4];
            unsigned long long b1 = *(const unsigned long long*)&Bs[k][tx * 4 + 2];
            float a0 = As[k][ty * 4 + 0];
            float a1 = As[k][ty * 4 + 1];
            float a2 = As[k][ty * 4 + 2];
            float a3 = As[k][ty * 4 + 3];
            unsigned long long p0 = pk2(a0, a0), p1 = pk2(a1, a1);
            unsigned long long p2 = pk2(a2, a2), p3 = pk2(a3, a3);
            fma2(acc2[0][0], p0, b0); fma2(acc2[0][1], p0, b1);
            fma2(acc2[1][0], p1, b0); fma2(acc2[1][1], p1, b1);
            fma2(acc2[2][0], p2, b0); fma2(acc2[2][1], p2, b1);
            fma2(acc2[3][0], p3, b0); fma2(acc2[3][1], p3, b1);
        }
        __syncthreads();
    }
#pragma unroll
    for (int i = 0; i < 4; i++) {
        int m = m0 + ty * 4 + i;
        if (m >= M) continue;
        float2 lo = upk2(acc2[i][0]);
        float2 hi = upk2(acc2[i][1]);
        float v[4] = {lo.x, lo.y, hi.x, hi.y};
#pragma unroll
        for (int j = 0; j < 4; j++) {
            int n = n0 + tx * 4 + j;
            if (n >= Nn) continue;
            float t = v[j];
            if (bias) t += bias[n];
            if (ACT == 1) t = 0.5f * t * (1.0f + erff(t * 0.70710678118654752f));
            C[(size_t)m * Nn + n] = t;
        }
    }
}

// final MLP layer: out[G, 6] = g_m2[G, 128] @ Wm3[128, 6] + bm3
__global__ void mlp3_kernel(const float* __restrict__ Wm3,
                            const float* __restrict__ bm3,
                            float* __restrict__ out) {
    int idx = blockIdx.x * blockDim.x + threadIdx.x;
    if (idx >= NG * 6) return;
    int m = idx / 6, n = idx % 6;
    const float* row = &g_m2[m * 128];
    float s = 0.f;
#pragma unroll 8
    for (int k = 0; k < 128; k++) s += row[k] * Wm3[k * 6 + n];
    out[idx] = s + bm3[n];
}

// ---------------- GCN aggregation + bias + BN + ReLU --------------------------
// one group of D4 threads per dst node; d = 4*D4 features; no float atomics
// OSEL: 1 -> g_H14, 2 -> g_H24
template <int D4, int OSEL>
__global__ void agg_kernel(const float* __restrict__ b,  const float* __restrict__ ga,
                           const float* __restrict__ be, const float* __restrict__ mm,
                           const float* __restrict__ vv) {
    float4* out = (OSEL == 1) ? g_H14 : g_H24;
    constexpr int NODES = 256 / D4;
    int node = blockIdx.x * NODES + (threadIdx.x / D4);
    int c    = threadIdx.x & (D4 - 1);
    if (node >= NNODES) return;

    float dn = g_dis[node];
    float w0 = dn * dn;                          // self-loop norm
    float4 t = g_T4[(size_t)node * D4 + c];
    float4 acc = make_float4(t.x * w0, t.y * w0, t.z * w0, t.w * w0);

    int e0 = g_off[node], e1 = g_off[node + 1];
    for (int e = e0; e < e1; e++) {
        int   s = g_srcS[e];
        float w = g_normS[e];
        float4 ts = g_T4[(size_t)s * D4 + c];
        acc.x += ts.x * w; acc.y += ts.y * w;
        acc.z += ts.z * w; acc.w += ts.w * w;
    }

    float bb[4] = {b[c*4],  b[c*4+1],  b[c*4+2],  b[c*4+3]};
    float gg[4] = {ga[c*4], ga[c*4+1], ga[c*4+2], ga[c*4+3]};
    float eb[4] = {be[c*4], be[c*4+1], be[c*4+2], be[c*4+3]};
    float mu[4] = {mm[c*4], mm[c*4+1], mm[c*4+2], mm[c*4+3]};
    float va[4] = {vv[c*4], vv[c*4+1], vv[c*4+2], vv[c*4+3]};
    float4 o;
    o.x = fmaxf((acc.x + bb[0] - mu[0]) * (gg[0] * rsqrtf(va[0] + EPSBN)) + eb[0], 0.f);
    o.y = fmaxf((acc.y + bb[1] - mu[1]) * (gg[1] * rsqrtf(va[1] + EPSBN)) + eb[1], 0.f);
    o.z = fmaxf((acc.z + bb[2] - mu[2]) * (gg[2] * rsqrtf(va[2] + EPSBN)) + eb[2], 0.f);
    o.w = fmaxf((acc.w + bb[3] - mu[3]) * (gg[3] * rsqrtf(va[3] + EPSBN)) + eb[3], 0.f);
    out[(size_t)node * D4 + c] = o;
}

// ---------------- pooling (batch is sorted -> run-length flush) ---------------
__global__ void pool_feat_kernel(const int* __restrict__ batch) {
    int c  = threadIdx.x;                  // 0..63 float4 columns (d = 256)
    int i0 = blockIdx.x * 64;
    if (i0 >= NNODES) return;
    int i1 = min(i0 + 64, NNODES);
    int cur = batch[i0];
    float4 s  = make_float4(0, 0, 0, 0);
    float4 mx = make_float4(0, 0, 0, 0);
    for (int i = i0; i < i1; i++) {
        int g = batch[i];
        if (g != cur) {
            int base = cur * 256 + c * 4;
            atomicAdd(&g_psum[base + 0], s.x); atomicAdd(&g_psum[base + 1], s.y);
            atomicAdd(&g_psum[base + 2], s.z); atomicAdd(&g_psum[base + 3], s.w);
            atomicMax(&g_pmax[base + 0], __float_as_uint(mx.x));
            atomicMax(&g_pmax[base + 1], __float_as_uint(mx.y));
            atomicMax(&g_pmax[base + 2], __float_as_uint(mx.z));
            atomicMax(&g_pmax[base + 3], __float_as_uint(mx.w));
            cur = g; s = make_float4(0, 0, 0, 0); mx = make_float4(0, 0, 0, 0);
        }
        float4 hv = g_H14[(size_t)i * 64 + c];
        s.x += hv.x; s.y += hv.y; s.z += hv.z; s.w += hv.w;
        mx.x = fmaxf(mx.x, hv.x); mx.y = fmaxf(mx.y, hv.y);
        mx.z = fmaxf(mx.z, hv.z); mx.w = fmaxf(mx.w, hv.w);
    }
    int base = cur * 256 + c * 4;
    atomicAdd(&g_psum[base + 0], s.x); atomicAdd(&g_psum[base + 1], s.y);
    atomicAdd(&g_psum[base + 2], s.z); atomicAdd(&g_psum[base + 3], s.w);
    atomicMax(&g_pmax[base + 0], __float_as_uint(mx.x));
    atomicMax(&g_pmax[base + 1], __float_as_uint(mx.y));
    atomicMax(&g_pmax[base + 2], __float_as_uint(mx.z));
    atomicMax(&g_pmax[base + 3], __float_as_uint(mx.w));
}

__global__ void pool_cnt_kernel(const int* __restrict__ batch) {
    int t  = blockIdx.x * blockDim.x + threadIdx.x;
    int i0 = t * 64;
    if (i0 >= NNODES) return;
    int i1 = min(i0 + 64, NNODES);
    int cur = batch[i0];
    int run = 0;
    for (int i = i0; i < i1; i++) {
        int g = batch[i];
        if (g != cur) { atomicAdd(&g_pcnt[cur], (float)run); cur = g; run = 0; }
        run++;
    }
    atomicAdd(&g_pcnt[cur], (float)run);
}

__global__ void finalize_z_kernel() {
    int idx = blockIdx.x * blockDim.x + threadIdx.x;
    if (idx >= NG * 512) return;
    int g = idx >> 9, c = idx & 511;
    if (c < 256) g_z[idx] = g_psum[g * 256 + c] / fmaxf(g_pcnt[g], 1.0f);
    else         g_z[idx] = __uint_as_float(g_pmax[g * 256 + (c - 256)]);
}

// ---------------- launch ------------------------------------------------------
extern "C" void kernel_launch(void* const* d_in, const int* in_sizes, int n_in,
                              void* d_out, int out_size) {
    const float* x     = (const float*)d_in[0];
    const int*   ei    = (const int*)d_in[1];   // [2, E] as int32
    const int*   batch = (const int*)d_in[2];
    const float *W1 = (const float*)d_in[3],  *b1 = (const float*)d_in[4],
                *ga1 = (const float*)d_in[5], *be1 = (const float*)d_in[6],
                *m1 = (const float*)d_in[7],  *v1 = (const float*)d_in[8];
    const float *W2 = (const float*)d_in[9],  *b2 = (const float*)d_in[10],
                *ga2 = (const float*)d_in[11],*be2 = (const float*)d_in[12],
                *m2 = (const float*)d_in[13], *v2 = (const float*)d_in[14];
    const float *W3 = (const float*)d_in[15], *b3 = (const float*)d_in[16],
                *ga3 = (const float*)d_in[17],*be3 = (const float*)d_in[18],
                *m3 = (const float*)d_in[19], *v3 = (const float*)d_in[20];
    const float *Wm1 = (const float*)d_in[21], *bm1 = (const float*)d_in[22];
    const float *Wm2 = (const float*)d_in[23], *bm2 = (const float*)d_in[24];
    const float *Wm3 = (const float*)d_in[25], *bm3 = (const float*)d_in[26];
    float* out = (float*)d_out;

    const int* src = ei;
    const int* dst = ei + NEDGES;

    // preprocessing
    zero_kernel<<<512, 256>>>();
    count_kernel<<<(NEDGES + 255) / 256, 256>>>(dst);
    scanA_kernel<<<NSCB, SCAN_B>>>();
    scanB_kernel<<<1, 128>>>();
    scanC_kernel<<<(NNODES + 255) / 256, 256>>>();
    fill_kernel<<<(NEDGES + 255) / 256, 256>>>(src, dst);

    const int MB = (NNODES + 63) / 64;   // 782 row-tiles

    // layer 1: 64 -> 128   (A = x ext, C = g_T4)
    gemm_kernel<0, 0, 1><<<dim3(MB, 2), 256>>>(x, W1, nullptr, nullptr, NNODES, 128, 64);
    agg_kernel<32, 1><<<(NNODES + 7) / 8, 256>>>(b1, ga1, be1, m1, v1);
    // layer 2: 128 -> 256  (A = g_H14, C = g_T4)
    gemm_kernel<0, 1, 1><<<dim3(MB, 4), 256>>>(nullptr, W2, nullptr, nullptr, NNODES, 256, 128);
    agg_kernel<64, 2><<<(NNODES + 3) / 4, 256>>>(b2, ga2, be2, m2, v2);
    // layer 3: 256 -> 256  (A = g_H24, C = g_T4)
    gemm_kernel<0, 2, 1><<<dim3(MB, 4), 256>>>(nullptr, W3, nullptr, nullptr, NNODES, 256, 256);
    agg_kernel<64, 1><<<(NNODES + 3) / 4, 256>>>(b3, ga3, be3, m3, v3);

    // pooling (reads g_H14)
    pool_feat_kernel<<<(NNODES + 63) / 64, 64>>>(batch);
    pool_cnt_kernel<<<((NNODES + 63) / 64 + 255) / 256, 256>>>(batch);
    finalize_z_kernel<<<(NG * 512 + 255) / 256, 256>>>();

    // MLP head
    gemm_kernel<1, 3, 2><<<dim3(8, 4), 256>>>(nullptr, Wm1, bm1, nullptr, NG, 256, 512);
    gemm_kernel<1, 4, 3><<<dim3(8, 2), 256>>>(nullptr, Wm2, bm2, nullptr, NG, 128, 256);
    mlp3_kernel<<<(NG * 6 + 255) / 256, 256>>>(Wm3, bm3, out);
}